// round 13
// baseline (speedup 1.0000x reference)
#include <cuda_runtime.h>
#include <cuda_bf16.h>
#include <cstdint>

// Shapes (fixed)
#define Bn   4
#define Hn   16
#define Tn   512
#define Mn   512
#define Dn   64
#define HIDn 16

typedef unsigned long long ull;

constexpr int NTH    = 512;
constexpr int TILE_T = 128;
constexpr int MCH    = 128;
constexpr int NCHUNK = 4;

constexpr int QKP    = 36;   // words/row, Q & K bf16 tiles [128][64]  (144 B)
constexpr int VTP    = 68;   // words/row, Vt bf16 [64][128]           (272 B)
constexpr int OPITCH = 72;   // words/row, O partial smem [128][64] f32

// buffer-relative offsets (bytes)
constexpr int BUF_KH  = 0;
constexpr int BUF_KL  = BUF_KH + TILE_T*QKP*4;     // 18432
constexpr int BUF_VTH = BUF_KL + TILE_T*QKP*4;     // 36864
constexpr int BUF_VTL = BUF_VTH + Dn*VTP*4;        // 54272
constexpr int BUF_SZ  = BUF_VTL + Dn*VTP*4;        // 71680

// smem layout
constexpr int SM_QH   = 0;
constexpr int SM_QL   = SM_QH + TILE_T*QKP*4;      // 18432
constexpr int SM_BUF0 = SM_QL + TILE_T*QKP*4;      // 36864
constexpr int SM_BUF1 = SM_BUF0 + BUF_SZ;          // 108544
constexpr int SM_OSM  = SM_BUF0;                   // overlay (end only)
constexpr int SM_PSUM = SM_BUF1 + BUF_SZ;          // 180224
constexpr int SM_W    = SM_PSUM + 2*TILE_T*4;      // 181248
constexpr int SMEM_BYTES = SM_W + 32*8;            // 181504

extern __shared__ char smem[];

// ---------- packed f32x2 helpers ----------
__device__ __forceinline__ ull pk2(float lo, float hi) {
    ull r; asm("mov.b64 %0, {%1,%2};" : "=l"(r) : "f"(lo), "f"(hi)); return r;
}
__device__ __forceinline__ ull dup2(float v) { return pk2(v, v); }
__device__ __forceinline__ void un2(ull v, float& a, float& b) {
    asm("mov.b64 {%0,%1}, %2;" : "=f"(a), "=f"(b) : "l"(v));
}
__device__ __forceinline__ ull f2fma(ull a, ull b, ull c) {
    ull d; asm("fma.rn.f32x2 %0, %1, %2, %3;" : "=l"(d) : "l"(a), "l"(b), "l"(c)); return d;
}
__device__ __forceinline__ ull f2add(ull a, ull b) {
    ull d; asm("add.rn.f32x2 %0, %1, %2;" : "=l"(d) : "l"(a), "l"(b)); return d;
}
// packed exp2(s*log2e + C)
__device__ __forceinline__ ull exp2p(ull s2, ull L2E2, ull C2) {
    const ull MAG2  = dup2(12582912.0f);
    const ull NONE2 = dup2(-1.0f);
    const ull ONE2  = dup2(1.0f);
    const ull TC1   = dup2(0.69314718056f);
    const ull TC2   = dup2(0.240226507f);
    const ull TC3   = dup2(0.0555041087f);
    const ull TC4   = dup2(0.00961812911f);
    const ull TC5   = dup2(0.00133335581f);
    ull a2  = f2fma(s2, L2E2, C2);
    ull fr2 = f2add(a2, MAG2);
    ull nf2 = f2fma(MAG2, NONE2, fr2);
    ull ff2 = f2fma(nf2, NONE2, a2);
    ull p2  = f2fma(TC5, ff2, TC4);
    p2 = f2fma(p2, ff2, TC3);
    p2 = f2fma(p2, ff2, TC2);
    p2 = f2fma(p2, ff2, TC1);
    p2 = f2fma(p2, ff2, ONE2);
    float frl, frh, pl, ph;
    un2(fr2, frl, frh); un2(p2, pl, ph);
    float yl = __int_as_float(__float_as_int(pl) + (__float_as_int(frl) << 23));
    float yh = __int_as_float(__float_as_int(ph) + (__float_as_int(frh) << 23));
    return pk2(yl, yh);
}

// pack two f32 into bf16x2 (lo -> low half)
__device__ __forceinline__ uint32_t bf16x2_of(float lo, float hi) {
    uint32_t r;
    asm("cvt.rn.bf16x2.f32 %0, %1, %2;" : "=r"(r) : "f"(hi), "f"(lo));
    return r;
}

// mma.sync m16n8k16 row.col f32.bf16.bf16.f32
__device__ __forceinline__ void mma16816(float* c, const uint32_t a[4], uint32_t b0, uint32_t b1) {
    asm volatile("mma.sync.aligned.m16n8k16.row.col.f32.bf16.bf16.f32 "
        "{%0,%1,%2,%3}, {%4,%5,%6,%7}, {%8,%9}, {%0,%1,%2,%3};"
        : "+f"(c[0]), "+f"(c[1]), "+f"(c[2]), "+f"(c[3])
        : "r"(a[0]), "r"(a[1]), "r"(a[2]), "r"(a[3]), "r"(b0), "r"(b1));
}

// ldmatrix x4 (sm_75+ baseline)
__device__ __forceinline__ void ldsm_x4(uint32_t* r, uint32_t saddr) {
    asm volatile("ldmatrix.sync.aligned.m8n8.x4.shared.b16 {%0,%1,%2,%3}, [%4];"
        : "=r"(r[0]), "=r"(r[1]), "=r"(r[2]), "=r"(r[3]) : "r"(saddr));
}

// fp32 float4 -> bf16 hi/lo splits stored as uint2
__device__ __forceinline__ void store_split(char* hib, char* lob, uint32_t byteoff, float4 v) {
    uint32_t h01 = bf16x2_of(v.x, v.y);
    uint32_t h23 = bf16x2_of(v.z, v.w);
    float r0 = v.x - __int_as_float(h01 << 16);
    float r1 = v.y - __int_as_float(h01 & 0xFFFF0000u);
    float r2 = v.z - __int_as_float(h23 << 16);
    float r3 = v.w - __int_as_float(h23 & 0xFFFF0000u);
    uint32_t l01 = bf16x2_of(r0, r1);
    uint32_t l23 = bf16x2_of(r2, r3);
    *reinterpret_cast<uint2*>(hib + byteoff) = make_uint2(h01, h23);
    *reinterpret_cast<uint2*>(lob + byteoff) = make_uint2(l01, l23);
}

// load K chunk -> [m][d] bf16 hi/lo, pitch 144B
__device__ __forceinline__ void load_K(const float* __restrict__ ks, char* buf, int tid) {
#pragma unroll
    for (int it = 0; it < 4; ++it) {
        int idx = tid + NTH * it;
        int row = idx >> 4, c4 = idx & 15;
        float4 v = *reinterpret_cast<const float4*>(ks + row * Dn + 4 * c4);
        store_split(buf + BUF_KH, buf + BUF_KL, row * 144 + c4 * 8, v);
    }
}
// load V chunk -> Vt[d][m-pair] bf16x2 hi/lo, conflict-free stores
__device__ __forceinline__ void load_V(const float* __restrict__ vs, char* buf, int tid) {
    uint32_t* VtH = reinterpret_cast<uint32_t*>(buf + BUF_VTH);
    uint32_t* VtL = reinterpret_cast<uint32_t*>(buf + BUF_VTL);
#pragma unroll
    for (int it = 0; it < 4; ++it) {
        int idx = tid + NTH * it;      // 0..2047
        int mp = idx & 63;             // m-pair 0..63
        int d  = (idx >> 6) * 2;       // 0,2,..,62
        float2 va = *reinterpret_cast<const float2*>(vs + (2*mp)   * Dn + d);
        float2 vb = *reinterpret_cast<const float2*>(vs + (2*mp+1) * Dn + d);
        uint32_t h0 = bf16x2_of(va.x, vb.x);
        uint32_t h1 = bf16x2_of(va.y, vb.y);
        float r0 = va.x - __int_as_float(h0 << 16);
        float r1 = vb.x - __int_as_float(h0 & 0xFFFF0000u);
        float r2 = va.y - __int_as_float(h1 << 16);
        float r3 = vb.y - __int_as_float(h1 & 0xFFFF0000u);
        uint32_t l0 = bf16x2_of(r0, r1);
        uint32_t l1 = bf16x2_of(r2, r3);
        VtH[d * VTP + mp]       = h0;
        VtH[(d+1) * VTP + mp]   = h1;
        VtL[d * VTP + mp]       = l0;
        VtL[(d+1) * VTP + mp]   = l1;
    }
}

__global__ __launch_bounds__(NTH, 1)
void msmha_mma_kernel(const float* __restrict__ qg, const float* __restrict__ kg,
                      const float* __restrict__ vg, const float* __restrict__ dtm,
                      const float* __restrict__ w1g, const float* __restrict__ b1g,
                      const float* __restrict__ w2g, const float* __restrict__ b2g,
                      float* __restrict__ outg)
{
    const int tt  = blockIdx.x;
    const int bh  = blockIdx.y;
    const int b   = bh >> 4;
    const int h   = bh & 15;
    const int t0  = tt * TILE_T;
    const int tid = threadIdx.x;
    const int wid = tid >> 5;
    const int lane = tid & 31;
    const int g = lane >> 2;
    const int t = lane & 3;
    const int wm = wid >> 1;
    const int wn = wid & 1;
    const int row0 = 16*wm + g;
    const int row1 = row0 + 8;

    // per-thread ldmatrix offsets
    const uint32_t aoff = (uint32_t)((lane & 15) * 144 + (lane >> 4) * 16);
    const uint32_t koff = (uint32_t)(((lane & 7) + (lane >> 4) * 8) * 144 + ((lane >> 3) & 1) * 16);
    const uint32_t voff = (uint32_t)(((lane & 7) + (lane >> 4) * 8) * 272 + ((lane >> 3) & 1) * 16);

    // ---- prologue: weight table + folds ----
    float Afold = 0.f, Bfold = 0.f, Cfold = 0.f;
    {
        const float* W1 = w1g + h * 2 * HIDn;
        const float* B1 = b1g + h * HIDn;
        const float* W2 = w2g + h * HIDn;
        if (tid < 8) {
            int jp = tid;
            ull* Wt = reinterpret_cast<ull*>(smem + SM_W);
            Wt[4*jp+0] = pk2(W1[2*jp],      W1[2*jp+1]);
            Wt[4*jp+1] = pk2(W1[16+2*jp],   W1[16+2*jp+1]);
            Wt[4*jp+2] = pk2(B1[2*jp],      B1[2*jp+1]);
            Wt[4*jp+3] = pk2(0.5f*W2[2*jp], 0.5f*W2[2*jp+1]);
        }
#pragma unroll
        for (int j = 0; j < 16; ++j) {
            float w2v = W2[j];
            Afold += w2v * W1[j];
            Bfold += w2v * W1[16+j];
            Cfold += w2v * B1[j];
        }
        Afold *= 0.5f; Bfold *= 0.5f; Cfold *= 0.5f;
    }
    const ull L2E2 = dup2(1.44269504f);
    const ull CEX2 = dup2((b2g[h] - 20.0f) * 1.44269504f);
    const ull ABSM = 0x7FFFFFFF7FFFFFFFull;

    // ---- Q tile (prescaled 1/8) ----
    {
        const float* qsrc = qg + ((long)bh * Tn + t0) * Dn;
#pragma unroll
        for (int it = 0; it < 4; ++it) {
            int idx = tid + NTH * it;
            int row = idx >> 4, c4 = idx & 15;
            float4 v = *reinterpret_cast<const float4*>(qsrc + row * Dn + 4 * c4);
            v.x *= 0.125f; v.y *= 0.125f; v.z *= 0.125f; v.w *= 0.125f;
            store_split(smem + SM_QH, smem + SM_QL, row * 144 + c4 * 8, v);
        }
    }
    // preload chunk 0
    load_K(kg + (long)bh * Mn * Dn, smem + SM_BUF0, tid);
    load_V(vg + (long)bh * Mn * Dn, smem + SM_BUF0, tid);
    __syncthreads();

    const uint32_t qh_b = (uint32_t)__cvta_generic_to_shared(smem + SM_QH) + (uint32_t)(16*wm*144) + aoff;
    const uint32_t ql_b = (uint32_t)__cvta_generic_to_shared(smem + SM_QL) + (uint32_t)(16*wm*144) + aoff;

    float rs0 = 0.f, rs1 = 0.f;
    float o[8][4];
#pragma unroll
    for (int i = 0; i < 8; ++i) { o[i][0]=o[i][1]=o[i][2]=o[i][3]=0.f; }

    for (int mc = 0; mc < NCHUNK; ++mc) {
        char* buf = smem + ((mc & 1) ? SM_BUF1 : SM_BUF0);
        const uint32_t kh_b = (uint32_t)__cvta_generic_to_shared(buf + BUF_KH) + (uint32_t)(64*wn*144) + koff;
        const uint32_t kl_b = (uint32_t)__cvta_generic_to_shared(buf + BUF_KL) + (uint32_t)(64*wn*144) + koff;
        const uint32_t vh_b = (uint32_t)__cvta_generic_to_shared(buf + BUF_VTH) + (uint32_t)(128*wn) + voff;
        const uint32_t vl_b = (uint32_t)__cvta_generic_to_shared(buf + BUF_VTL) + (uint32_t)(128*wn) + voff;

        // ===== QK^T =====
        float s[8][4];
#pragma unroll
        for (int i = 0; i < 8; ++i) { s[i][0]=s[i][1]=s[i][2]=s[i][3]=0.f; }
#pragma unroll
        for (int kc = 0; kc < 4; ++kc) {
            uint32_t ah[4], al[4];
            ldsm_x4(ah, qh_b + 32*kc);
            ldsm_x4(al, ql_b + 32*kc);
#pragma unroll
            for (int tp = 0; tp < 4; ++tp) {
                uint32_t kh[4], kl[4];
                ldsm_x4(kh, kh_b + (uint32_t)(16*tp*144) + 32*kc);
                ldsm_x4(kl, kl_b + (uint32_t)(16*tp*144) + 32*kc);
                mma16816(s[2*tp],   ah, kh[0], kh[1]);
                mma16816(s[2*tp],   ah, kl[0], kl[1]);
                mma16816(s[2*tp],   al, kh[0], kh[1]);
                mma16816(s[2*tp+1], ah, kh[2], kh[3]);
                mma16816(s[2*tp+1], ah, kl[2], kl[3]);
                mma16816(s[2*tp+1], al, kh[2], kh[3]);
            }
        }

        // ===== MLP + exp -> P fragments =====
        ull wA[8], wB[8], wC[8], wH[8];
        {
            const ull* Wt = reinterpret_cast<const ull*>(smem + SM_W);
#pragma unroll
            for (int jp = 0; jp < 8; ++jp) {
                wA[jp] = Wt[4*jp]; wB[jp] = Wt[4*jp+1];
                wC[jp] = Wt[4*jp+2]; wH[jp] = Wt[4*jp+3];
            }
        }
        uint32_t ph[4][4], pl[4][4];
        const float* dbase = dtm + ((long)b * Tn + t0) * Mn + mc * MCH + 64*wn;
#pragma unroll
        for (int ti = 0; ti < 8; ++ti) {
            const int colb = 8*ti + 2*t;
            float2 d01 = *reinterpret_cast<const float2*>(dbase + (long)row0 * Mn + colb);
            float2 d23 = *reinterpret_cast<const float2*>(dbase + (long)row1 * Mn + colb);
            float Dv[4] = {d01.x, d01.y, d23.x, d23.y};
            float pv[4];
#pragma unroll
            for (int e = 0; e < 4; ++e) {
                float dotv = s[ti][e];
                ull dd = dup2(dotv), DD = dup2(Dv[e]);
                ull acc = 0ull;
#pragma unroll
                for (int jp = 0; jp < 8; ++jp) {
                    ull x = f2fma(dd, wA[jp], f2fma(DD, wB[jp], wC[jp]));
                    acc = f2fma(x & ABSM, wH[jp], acc);
                }
                float alo, ahi; un2(acc, alo, ahi);
                pv[e] = (alo + ahi) + fmaf(dotv, Afold, fmaf(Dv[e], Bfold, Cfold));
            }
            ull y01 = exp2p(pk2(pv[0], pv[1]), L2E2, CEX2);
            ull y23 = exp2p(pk2(pv[2], pv[3]), L2E2, CEX2);
            float p0, p1, p2, p3;
            un2(y01, p0, p1); un2(y23, p2, p3);
            rs0 += p0 + p1;  rs1 += p2 + p3;
            uint32_t h01 = bf16x2_of(p0, p1);
            uint32_t h23 = bf16x2_of(p2, p3);
            float r0 = p0 - __int_as_float(h01 << 16);
            float r1 = p1 - __int_as_float(h01 & 0xFFFF0000u);
            float r2 = p2 - __int_as_float(h23 << 16);
            float r3 = p3 - __int_as_float(h23 & 0xFFFF0000u);
            uint32_t l01 = bf16x2_of(r0, r1);
            uint32_t l23 = bf16x2_of(r2, r3);
            const int kc = ti >> 1, half = (ti & 1) * 2;
            ph[kc][half] = h01; ph[kc][half+1] = h23;
            pl[kc][half] = l01; pl[kc][half+1] = l23;
        }

        // ===== P @ V -> persistent O registers =====
#pragma unroll
        for (int kc = 0; kc < 4; ++kc) {
#pragma unroll
            for (int tp = 0; tp < 4; ++tp) {
                uint32_t vh[4], vl[4];
                ldsm_x4(vh, vh_b + (uint32_t)(16*tp*272) + 32*kc);
                ldsm_x4(vl, vl_b + (uint32_t)(16*tp*272) + 32*kc);
                mma16816(o[2*tp],   ph[kc], vh[0], vh[1]);
                mma16816(o[2*tp],   ph[kc], vl[0], vl[1]);
                mma16816(o[2*tp],   pl[kc], vh[0], vh[1]);
                mma16816(o[2*tp+1], ph[kc], vh[2], vh[3]);
                mma16816(o[2*tp+1], ph[kc], vl[2], vl[3]);
                mma16816(o[2*tp+1], pl[kc], vh[2], vh[3]);
            }
        }

        // load next chunk into other buffer
        if (mc < NCHUNK - 1) {
            char* nbuf = smem + (((mc + 1) & 1) ? SM_BUF1 : SM_BUF0);
            const long base = (long)bh * Mn * Dn + (long)(mc + 1) * MCH * Dn;
            load_K(kg + base, nbuf, tid);
            load_V(vg + base, nbuf, tid);
        }
        __syncthreads();
    }

    // rowsums
    rs0 += __shfl_xor_sync(0xffffffffu, rs0, 1);
    rs0 += __shfl_xor_sync(0xffffffffu, rs0, 2);
    rs1 += __shfl_xor_sync(0xffffffffu, rs1, 1);
    rs1 += __shfl_xor_sync(0xffffffffu, rs1, 2);
    if (t == 0) {
        float* Ps = reinterpret_cast<float*>(smem + SM_PSUM);
        Ps[wn * TILE_T + row0] = rs0;
        Ps[wn * TILE_T + row1] = rs1;
    }

    // flush O registers once (overlay on buffers)
    {
        float* Ob = reinterpret_cast<float*>(smem + SM_OSM) + wn * TILE_T * OPITCH;
#pragma unroll
        for (int ti = 0; ti < 8; ++ti) {
            const int c = 8*ti + 2*t;
            *reinterpret_cast<float2*>(Ob + row0 * OPITCH + c) = make_float2(o[ti][0], o[ti][1]);
            *reinterpret_cast<float2*>(Ob + row1 * OPITCH + c) = make_float2(o[ti][2], o[ti][3]);
        }
    }
    __syncthreads();

    // epilogue: reduce halves, normalize, store
    {
        const float* Ps = reinterpret_cast<const float*>(smem + SM_PSUM);
        const float* O0 = reinterpret_cast<const float*>(smem + SM_OSM);
        const float* O1 = O0 + TILE_T * OPITCH;
#pragma unroll
        for (int it = 0; it < 4; ++it) {
            int idx = tid + NTH * it;
            int row = idx >> 4, c4 = idx & 15;
            float4 a  = *reinterpret_cast<const float4*>(O0 + row * OPITCH + 4*c4);
            float4 bq = *reinterpret_cast<const float4*>(O1 + row * OPITCH + 4*c4);
            float inv = 1.0f / (Ps[row] + Ps[TILE_T + row]);
            float4 rr = make_float4((a.x+bq.x)*inv, (a.y+bq.y)*inv,
                                    (a.z+bq.z)*inv, (a.w+bq.w)*inv);
            *reinterpret_cast<float4*>(outg + ((long)b*Tn + t0 + row)*(Hn*Dn) + h*Dn + 4*c4) = rr;
        }
    }
}

extern "C" void kernel_launch(void* const* d_in, const int* in_sizes, int n_in,
                              void* d_out, int out_size)
{
    const float* q   = (const float*)d_in[0];
    const float* k   = (const float*)d_in[1];
    const float* v   = (const float*)d_in[2];
    const float* dtm = (const float*)d_in[3];
    const float* w1  = (const float*)d_in[4];
    const float* b1  = (const float*)d_in[5];
    const float* w2  = (const float*)d_in[6];
    const float* b2  = (const float*)d_in[7];
    float* out = (float*)d_out;

    cudaFuncSetAttribute(msmha_mma_kernel,
                         cudaFuncAttributeMaxDynamicSharedMemorySize, SMEM_BYTES);

    dim3 grid(Tn / TILE_T, Bn * Hn);   // (4, 64) = 256 CTAs
    msmha_mma_kernel<<<grid, NTH, SMEM_BYTES>>>(q, k, v, dtm, w1, b1, w2, b2, out);
}

// round 15
// speedup vs baseline: 1.1129x; 1.1129x over previous
#include <cuda_runtime.h>
#include <cuda_bf16.h>
#include <cstdint>

// Shapes (fixed)
#define Bn   4
#define Hn   16
#define Tn   512
#define Mn   512
#define Dn   64
#define HIDn 16

typedef unsigned long long ull;

constexpr int NTH    = 512;
constexpr int TILE_T = 128;
constexpr int MCH    = 128;
constexpr int NCHUNK = 4;

constexpr int OPITCH = 72;   // words/row, O partial smem [128][64] f32

// K/V tiles: [rows][64 d] bf16, row pitch 144 B (36 words)
constexpr int BUF_KH  = 0;
constexpr int BUF_KL  = BUF_KH + TILE_T*144;   // 18432
constexpr int BUF_VH  = BUF_KL + TILE_T*144;   // 36864
constexpr int BUF_VL  = BUF_VH + TILE_T*144;   // 55296
constexpr int BUF_SZ  = BUF_VL + TILE_T*144;   // 73728

constexpr int SM_QH   = 0;
constexpr int SM_QL   = SM_QH + TILE_T*144;    // 18432
constexpr int SM_BUF0 = SM_QL + TILE_T*144;    // 36864
constexpr int SM_BUF1 = SM_BUF0 + BUF_SZ;      // 110592
constexpr int SM_OSM  = SM_BUF0;               // overlay (end only)
constexpr int SM_PSUM = SM_BUF1 + BUF_SZ;      // 184320
constexpr int SM_W    = SM_PSUM + 2*TILE_T*4;  // 185344
constexpr int SMEM_BYTES = SM_W + 32*8;        // 185600

extern __shared__ char smem[];

// ---- device scratch: bf16 hi/lo K and V, [bh][m] rows of 32 words ----
__device__ uint32_t g_KH[1 << 20];
__device__ uint32_t g_KL[1 << 20];
__device__ uint32_t g_VH[1 << 20];
__device__ uint32_t g_VL[1 << 20];

// ---------- packed f32x2 helpers ----------
__device__ __forceinline__ ull pk2(float lo, float hi) {
    ull r; asm("mov.b64 %0, {%1,%2};" : "=l"(r) : "f"(lo), "f"(hi)); return r;
}
__device__ __forceinline__ ull dup2(float v) { return pk2(v, v); }
__device__ __forceinline__ void un2(ull v, float& a, float& b) {
    asm("mov.b64 {%0,%1}, %2;" : "=f"(a), "=f"(b) : "l"(v));
}
__device__ __forceinline__ ull f2fma(ull a, ull b, ull c) {
    ull d; asm("fma.rn.f32x2 %0, %1, %2, %3;" : "=l"(d) : "l"(a), "l"(b), "l"(c)); return d;
}
__device__ __forceinline__ ull f2add(ull a, ull b) {
    ull d; asm("add.rn.f32x2 %0, %1, %2;" : "=l"(d) : "l"(a), "l"(b)); return d;
}
// packed exp2(s*log2e + C)
__device__ __forceinline__ ull exp2p(ull s2, ull L2E2, ull C2) {
    const ull MAG2  = dup2(12582912.0f);
    const ull NONE2 = dup2(-1.0f);
    const ull ONE2  = dup2(1.0f);
    const ull TC1   = dup2(0.69314718056f);
    const ull TC2   = dup2(0.240226507f);
    const ull TC3   = dup2(0.0555041087f);
    const ull TC4   = dup2(0.00961812911f);
    const ull TC5   = dup2(0.00133335581f);
    ull a2  = f2fma(s2, L2E2, C2);
    ull fr2 = f2add(a2, MAG2);
    ull nf2 = f2fma(MAG2, NONE2, fr2);
    ull ff2 = f2fma(nf2, NONE2, a2);
    ull p2  = f2fma(TC5, ff2, TC4);
    p2 = f2fma(p2, ff2, TC3);
    p2 = f2fma(p2, ff2, TC2);
    p2 = f2fma(p2, ff2, TC1);
    p2 = f2fma(p2, ff2, ONE2);
    float frl, frh, pl, ph;
    un2(fr2, frl, frh); un2(p2, pl, ph);
    float yl = __int_as_float(__float_as_int(pl) + (__float_as_int(frl) << 23));
    float yh = __int_as_float(__float_as_int(ph) + (__float_as_int(frh) << 23));
    return pk2(yl, yh);
}

__device__ __forceinline__ uint32_t bf16x2_of(float lo, float hi) {
    uint32_t r;
    asm("cvt.rn.bf16x2.f32 %0, %1, %2;" : "=r"(r) : "f"(hi), "f"(lo));
    return r;
}

__device__ __forceinline__ void mma16816(float* c, const uint32_t a[4], uint32_t b0, uint32_t b1) {
    asm volatile("mma.sync.aligned.m16n8k16.row.col.f32.bf16.bf16.f32 "
        "{%0,%1,%2,%3}, {%4,%5,%6,%7}, {%8,%9}, {%0,%1,%2,%3};"
        : "+f"(c[0]), "+f"(c[1]), "+f"(c[2]), "+f"(c[3])
        : "r"(a[0]), "r"(a[1]), "r"(a[2]), "r"(a[3]), "r"(b0), "r"(b1));
}
__device__ __forceinline__ void ldsm_x4(uint32_t* r, uint32_t saddr) {
    asm volatile("ldmatrix.sync.aligned.m8n8.x4.shared.b16 {%0,%1,%2,%3}, [%4];"
        : "=r"(r[0]), "=r"(r[1]), "=r"(r[2]), "=r"(r[3]) : "r"(saddr));
}
__device__ __forceinline__ void ldsm_x4_t(uint32_t* r, uint32_t saddr) {
    asm volatile("ldmatrix.sync.aligned.m8n8.x4.trans.shared.b16 {%0,%1,%2,%3}, [%4];"
        : "=r"(r[0]), "=r"(r[1]), "=r"(r[2]), "=r"(r[3]) : "r"(saddr));
}

// fp32 float4 -> bf16 hi/lo uint2 pair
__device__ __forceinline__ void split4(float4 v, uint2& hi, uint2& lo) {
    uint32_t h01 = bf16x2_of(v.x, v.y);
    uint32_t h23 = bf16x2_of(v.z, v.w);
    float r0 = v.x - __int_as_float(h01 << 16);
    float r1 = v.y - __int_as_float(h01 & 0xFFFF0000u);
    float r2 = v.z - __int_as_float(h23 << 16);
    float r3 = v.w - __int_as_float(h23 & 0xFFFF0000u);
    hi = make_uint2(h01, h23);
    lo = make_uint2(bf16x2_of(r0, r1), bf16x2_of(r2, r3));
}

// ---------------- prepass: K,V fp32 -> bf16 hi/lo global ----------------
// Each source row (64 floats, 16 float4) becomes 32 hi words + 32 lo words.
// As uint2*, row stride is 16; element f4 of a row lands at row*16 + f4.
__global__ __launch_bounds__(256, 4)
void prep_kernel(const float* __restrict__ kg, const float* __restrict__ vg)
{
    const int bh    = blockIdx.x & 63;
    const int which = blockIdx.x >> 6;
    const float4* src = reinterpret_cast<const float4*>(which ? vg : kg);
    uint2* GH = reinterpret_cast<uint2*>(which ? g_VH : g_KH);
    uint2* GL = reinterpret_cast<uint2*>(which ? g_VL : g_KL);
#pragma unroll 4
    for (int it = 0; it < 32; ++it) {
        int u = threadIdx.x + 256 * it;        // 0..8191
        int m = u >> 4, f4 = u & 15;
        float4 v = src[((long)bh * 512 + m) * 16 + f4];
        uint2 hi, lo;
        split4(v, hi, lo);
        long o = ((long)bh * 512 + m) * 16 + f4;   // FIXED: was 2*f4 (OOB)
        GH[o] = hi;
        GL[o] = lo;
    }
}

// copy loader: global bf16 rows -> smem rows (pitch 144B)
__device__ __forceinline__ void copy_tile(const uint4* __restrict__ GH,
                                          const uint4* __restrict__ GL,
                                          char* bufH, char* bufL,
                                          long base_row, int tid) {
#pragma unroll
    for (int it = 0; it < 2; ++it) {
        int idx = tid + NTH * it;          // 0..1023
        int row = idx >> 3, q = idx & 7;   // 8 x uint4 per 32-word row
        uint4 a = GH[(base_row + row) * 8 + q];
        uint4 b = GL[(base_row + row) * 8 + q];
        *reinterpret_cast<uint4*>(bufH + row * 144 + q * 16) = a;
        *reinterpret_cast<uint4*>(bufL + row * 144 + q * 16) = b;
    }
}

__global__ __launch_bounds__(NTH, 1)
void msmha_mma_kernel(const float* __restrict__ qg,
                      const float* __restrict__ dtm,
                      const float* __restrict__ w1g, const float* __restrict__ b1g,
                      const float* __restrict__ w2g, const float* __restrict__ b2g,
                      float* __restrict__ outg)
{
    const int tt  = blockIdx.x;
    const int bh  = blockIdx.y;
    const int b   = bh >> 4;
    const int h   = bh & 15;
    const int t0  = tt * TILE_T;
    const int tid = threadIdx.x;
    const int wid = tid >> 5;
    const int lane = tid & 31;
    const int g = lane >> 2;
    const int t = lane & 3;
    const int wm = wid >> 1;
    const int wn = wid & 1;
    const int row0 = 16*wm + g;
    const int row1 = row0 + 8;

    // ldmatrix per-thread offsets
    const uint32_t aoff  = (uint32_t)((lane & 15) * 144 + (lane >> 4) * 16);  // A (row-major)
    const uint32_t koff  = (uint32_t)(((lane & 7) + ((lane >> 4) << 3)) * 144 + ((lane >> 3) & 1) * 16); // B K-rows
    const uint32_t vtoff = aoff;                                              // B via trans on [m][d] rows

    // ---- weight table + folds ----
    float Afold = 0.f, Bfold = 0.f, Cfold = 0.f;
    {
        const float* W1 = w1g + h * 2 * HIDn;
        const float* B1 = b1g + h * HIDn;
        const float* W2 = w2g + h * HIDn;
        if (tid < 8) {
            int jp = tid;
            ull* Wt = reinterpret_cast<ull*>(smem + SM_W);
            Wt[4*jp+0] = pk2(W1[2*jp],      W1[2*jp+1]);
            Wt[4*jp+1] = pk2(W1[16+2*jp],   W1[16+2*jp+1]);
            Wt[4*jp+2] = pk2(B1[2*jp],      B1[2*jp+1]);
            Wt[4*jp+3] = pk2(0.5f*W2[2*jp], 0.5f*W2[2*jp+1]);
        }
#pragma unroll
        for (int j = 0; j < 16; ++j) {
            float w2v = W2[j];
            Afold += w2v * W1[j];
            Bfold += w2v * W1[16+j];
            Cfold += w2v * B1[j];
        }
        Afold *= 0.5f; Bfold *= 0.5f; Cfold *= 0.5f;
    }
    const ull L2E2 = dup2(1.44269504f);
    const ull CEX2 = dup2((b2g[h] - 20.0f) * 1.44269504f);
    const ull ABSM = 0x7FFFFFFF7FFFFFFFull;

    // ---- Q tile (prescaled 1/8) -> bf16 hi/lo ----
    {
        const float* qsrc = qg + ((long)bh * Tn + t0) * Dn;
#pragma unroll
        for (int it = 0; it < 4; ++it) {
            int idx = tid + NTH * it;
            int row = idx >> 4, c4 = idx & 15;
            float4 v = *reinterpret_cast<const float4*>(qsrc + row * Dn + 4 * c4);
            v.x *= 0.125f; v.y *= 0.125f; v.z *= 0.125f; v.w *= 0.125f;
            uint2 hi, lo;
            split4(v, hi, lo);
            *reinterpret_cast<uint2*>(smem + SM_QH + row * 144 + c4 * 8) = hi;
            *reinterpret_cast<uint2*>(smem + SM_QL + row * 144 + c4 * 8) = lo;
        }
    }
    // preload chunk 0
    const uint4* KH4 = reinterpret_cast<const uint4*>(g_KH);
    const uint4* KL4 = reinterpret_cast<const uint4*>(g_KL);
    const uint4* VH4 = reinterpret_cast<const uint4*>(g_VH);
    const uint4* VL4 = reinterpret_cast<const uint4*>(g_VL);
    copy_tile(KH4, KL4, smem + SM_BUF0 + BUF_KH, smem + SM_BUF0 + BUF_KL, (long)bh * 512, tid);
    copy_tile(VH4, VL4, smem + SM_BUF0 + BUF_VH, smem + SM_BUF0 + BUF_VL, (long)bh * 512, tid);
    __syncthreads();

    const uint32_t qh_b = (uint32_t)__cvta_generic_to_shared(smem + SM_QH) + (uint32_t)(16*wm*144) + aoff;
    const uint32_t ql_b = (uint32_t)__cvta_generic_to_shared(smem + SM_QL) + (uint32_t)(16*wm*144) + aoff;

    float rs0 = 0.f, rs1 = 0.f;
    float o[8][4];
#pragma unroll
    for (int i = 0; i < 8; ++i) { o[i][0]=o[i][1]=o[i][2]=o[i][3]=0.f; }

    for (int mc = 0; mc < NCHUNK; ++mc) {
        char* buf = smem + ((mc & 1) ? SM_BUF1 : SM_BUF0);
        const uint32_t kh_b = (uint32_t)__cvta_generic_to_shared(buf + BUF_KH) + (uint32_t)(64*wn*144) + koff;
        const uint32_t kl_b = (uint32_t)__cvta_generic_to_shared(buf + BUF_KL) + (uint32_t)(64*wn*144) + koff;
        const uint32_t vh_b = (uint32_t)__cvta_generic_to_shared(buf + BUF_VH) + (uint32_t)(64*wn*144) + vtoff;
        const uint32_t vl_b = (uint32_t)__cvta_generic_to_shared(buf + BUF_VL) + (uint32_t)(64*wn*144) + vtoff;

        // ===== QK^T (interleaved accumulators) =====
        float s[8][4];
#pragma unroll
        for (int i = 0; i < 8; ++i) { s[i][0]=s[i][1]=s[i][2]=s[i][3]=0.f; }
#pragma unroll
        for (int kc = 0; kc < 4; ++kc) {
            uint32_t ah[4], al[4];
            ldsm_x4(ah, qh_b + 32*kc);
            ldsm_x4(al, ql_b + 32*kc);
#pragma unroll
            for (int tp = 0; tp < 4; ++tp) {
                uint32_t kh[4], kl[4];
                ldsm_x4(kh, kh_b + (uint32_t)(16*tp*144) + 32*kc);
                ldsm_x4(kl, kl_b + (uint32_t)(16*tp*144) + 32*kc);
                mma16816(s[2*tp],   ah, kh[0], kh[1]);
                mma16816(s[2*tp+1], ah, kh[2], kh[3]);
                mma16816(s[2*tp],   ah, kl[0], kl[1]);
                mma16816(s[2*tp+1], ah, kl[2], kl[3]);
                mma16816(s[2*tp],   al, kh[0], kh[1]);
                mma16816(s[2*tp+1], al, kh[2], kh[3]);
            }
        }

        // ===== MLP + exp -> P fragments =====
        ull wA[8], wB[8], wC[8], wH[8];
        {
            const ull* Wt = reinterpret_cast<const ull*>(smem + SM_W);
#pragma unroll
            for (int jp = 0; jp < 8; ++jp) {
                wA[jp] = Wt[4*jp]; wB[jp] = Wt[4*jp+1];
                wC[jp] = Wt[4*jp+2]; wH[jp] = Wt[4*jp+3];
            }
        }
        uint32_t ph[4][4], pl[4][4];
        const float* dbase = dtm + ((long)b * Tn + t0) * Mn + mc * MCH + 64*wn;
#pragma unroll
        for (int ti = 0; ti < 8; ++ti) {
            const int colb = 8*ti + 2*t;
            float2 d01 = *reinterpret_cast<const float2*>(dbase + (long)row0 * Mn + colb);
            float2 d23 = *reinterpret_cast<const float2*>(dbase + (long)row1 * Mn + colb);
            float Dv[4] = {d01.x, d01.y, d23.x, d23.y};
            float pv[4];
#pragma unroll
            for (int e = 0; e < 4; ++e) {
                float dotv = s[ti][e];
                ull dd = dup2(dotv), DD = dup2(Dv[e]);
                ull acc = 0ull;
#pragma unroll
                for (int jp = 0; jp < 8; ++jp) {
                    ull x = f2fma(dd, wA[jp], f2fma(DD, wB[jp], wC[jp]));
                    acc = f2fma(x & ABSM, wH[jp], acc);
                }
                float alo, ahi; un2(acc, alo, ahi);
                pv[e] = (alo + ahi) + fmaf(dotv, Afold, fmaf(Dv[e], Bfold, Cfold));
            }
            ull y01 = exp2p(pk2(pv[0], pv[1]), L2E2, CEX2);
            ull y23 = exp2p(pk2(pv[2], pv[3]), L2E2, CEX2);
            float p0, p1, p2, p3;
            un2(y01, p0, p1); un2(y23, p2, p3);
            rs0 += p0 + p1;  rs1 += p2 + p3;
            uint32_t h01 = bf16x2_of(p0, p1);
            uint32_t h23 = bf16x2_of(p2, p3);
            float r0 = p0 - __int_as_float(h01 << 16);
            float r1 = p1 - __int_as_float(h01 & 0xFFFF0000u);
            float r2 = p2 - __int_as_float(h23 << 16);
            float r3 = p3 - __int_as_float(h23 & 0xFFFF0000u);
            uint32_t l01 = bf16x2_of(r0, r1);
            uint32_t l23 = bf16x2_of(r2, r3);
            const int kc = ti >> 1, half = (ti & 1) * 2;
            ph[kc][half] = h01; ph[kc][half+1] = h23;
            pl[kc][half] = l01; pl[kc][half+1] = l23;
        }

        // ===== P @ V (ldmatrix.trans on [m][d] V rows) =====
#pragma unroll
        for (int kc = 0; kc < 4; ++kc) {
#pragma unroll
            for (int tp = 0; tp < 4; ++tp) {
                uint32_t vh[4], vl[4];
                ldsm_x4_t(vh, vh_b + (uint32_t)(16*kc*144) + 32*tp);
                ldsm_x4_t(vl, vl_b + (uint32_t)(16*kc*144) + 32*tp);
                mma16816(o[2*tp],   ph[kc], vh[0], vh[1]);
                mma16816(o[2*tp+1], ph[kc], vh[2], vh[3]);
                mma16816(o[2*tp],   ph[kc], vl[0], vl[1]);
                mma16816(o[2*tp+1], ph[kc], vl[2], vl[3]);
                mma16816(o[2*tp],   pl[kc], vh[0], vh[1]);
                mma16816(o[2*tp+1], pl[kc], vh[2], vh[3]);
            }
        }

        // load next chunk
        if (mc < NCHUNK - 1) {
            char* nbuf = smem + (((mc + 1) & 1) ? SM_BUF1 : SM_BUF0);
            const long base = (long)bh * 512 + (long)(mc + 1) * MCH;
            copy_tile(KH4, KL4, nbuf + BUF_KH, nbuf + BUF_KL, base, tid);
            copy_tile(VH4, VL4, nbuf + BUF_VH, nbuf + BUF_VL, base, tid);
        }
        __syncthreads();
    }

    // rowsums
    rs0 += __shfl_xor_sync(0xffffffffu, rs0, 1);
    rs0 += __shfl_xor_sync(0xffffffffu, rs0, 2);
    rs1 += __shfl_xor_sync(0xffffffffu, rs1, 1);
    rs1 += __shfl_xor_sync(0xffffffffu, rs1, 2);
    if (t == 0) {
        float* Ps = reinterpret_cast<float*>(smem + SM_PSUM);
        Ps[wn * TILE_T + row0] = rs0;
        Ps[wn * TILE_T + row1] = rs1;
    }

    // flush O registers (overlay on buffers)
    {
        float* Ob = reinterpret_cast<float*>(smem + SM_OSM) + wn * TILE_T * OPITCH;
#pragma unroll
        for (int ti = 0; ti < 8; ++ti) {
            const int c = 8*ti + 2*t;
            *reinterpret_cast<float2*>(Ob + row0 * OPITCH + c) = make_float2(o[ti][0], o[ti][1]);
            *reinterpret_cast<float2*>(Ob + row1 * OPITCH + c) = make_float2(o[ti][2], o[ti][3]);
        }
    }
    __syncthreads();

    // epilogue
    {
        const float* Ps = reinterpret_cast<const float*>(smem + SM_PSUM);
        const float* O0 = reinterpret_cast<const float*>(smem + SM_OSM);
        const float* O1 = O0 + TILE_T * OPITCH;
#pragma unroll
        for (int it = 0; it < 4; ++it) {
            int idx = tid + NTH * it;
            int row = idx >> 4, c4 = idx & 15;
            float4 a  = *reinterpret_cast<const float4*>(O0 + row * OPITCH + 4*c4);
            float4 bq = *reinterpret_cast<const float4*>(O1 + row * OPITCH + 4*c4);
            float inv = 1.0f / (Ps[row] + Ps[TILE_T + row]);
            float4 rr = make_float4((a.x+bq.x)*inv, (a.y+bq.y)*inv,
                                    (a.z+bq.z)*inv, (a.w+bq.w)*inv);
            *reinterpret_cast<float4*>(outg + ((long)b*Tn + t0 + row)*(Hn*Dn) + h*Dn + 4*c4) = rr;
        }
    }
}

extern "C" void kernel_launch(void* const* d_in, const int* in_sizes, int n_in,
                              void* d_out, int out_size)
{
    const float* q   = (const float*)d_in[0];
    const float* k   = (const float*)d_in[1];
    const float* v   = (const float*)d_in[2];
    const float* dtm = (const float*)d_in[3];
    const float* w1  = (const float*)d_in[4];
    const float* b1  = (const float*)d_in[5];
    const float* w2  = (const float*)d_in[6];
    const float* b2  = (const float*)d_in[7];
    float* out = (float*)d_out;

    prep_kernel<<<128, 256>>>(k, v);

    cudaFuncSetAttribute(msmha_mma_kernel,
                         cudaFuncAttributeMaxDynamicSharedMemorySize, SMEM_BYTES);
    dim3 grid(Tn / TILE_T, Bn * Hn);   // (4, 64) = 256 CTAs
    msmha_mma_kernel<<<grid, NTH, SMEM_BYTES>>>(q, dtm, w1, b1, w2, b2, out);
}